// round 9
// baseline (speedup 1.0000x reference)
#include <cuda_runtime.h>
#include <math.h>
#include <cstdint>

#define LSEQ   1024
#define NBATCH 64
#define NCH    64
#define NSTEP  1056          /* steps per strip: 1024 + 31 + pad */
#define BIGC   1.0e10f
#define LOG2E  1.4426950408889634f
#define LN2F   0.6931471805599453f

/* Strip-step-major scratch: g_D1[b][w][s][l] = D[32w+l][s-l] * log2(e).
   277 MB. Slots with s-l outside [0,1023] are never written and stay 0. */
__device__ float g_D1[(size_t)NBATCH * 32 * NSTEP * 32];

__device__ __forceinline__ float ex2(float z) {
    float r; asm("ex2.approx.f32 %0, %1;" : "=f"(r) : "f"(z)); return r;
}
__device__ __forceinline__ float lg2(float z) {
    float r; asm("lg2.approx.f32 %0, %1;" : "=f"(r) : "f"(z)); return r;
}
__device__ __forceinline__ uint32_t f2tf32(float v) {
    uint32_t r; asm("cvt.rna.tf32.f32 %0, %1;" : "=r"(r) : "f"(v)); return r;
}
__device__ __forceinline__ uint32_t smem_u32(const void* p) {
    uint32_t a;
    asm("{ .reg .u64 t; cvta.to.shared.u64 t, %1; cvt.u32.u64 %0, t; }" : "=r"(a) : "l"(p));
    return a;
}
/* softmin in base-2 domain: -log2(2^-a + 2^-u + 2^-lf), 3 MUFU */
__device__ __forceinline__ float softmin3(float a, float u, float lf) {
    float mn1 = fminf(a, u);
    float mx1 = fmaxf(a, u);
    float m   = fminf(mn1, lf);
    float M   = fmaxf(mx1, lf);
    float med = fmaxf(mn1, fminf(mx1, lf));
    float e   = 1.0f + ex2(m - med) + ex2(m - M);
    return m - lg2(e);
}

/* ------------------------------------------------------------------ */
/* Kernel A: D = (x2 + y2 - 2*x.y^T) * log2(e) via tf32 mma.sync,     */
/* written into the strip-step-major layout g_D1. (unchanged from R8)  */
/* ------------------------------------------------------------------ */
__global__ void __launch_bounds__(256)
compute_D_kernel(const float* __restrict__ x, const float* __restrict__ y) {
    const int b  = blockIdx.y;
    const int ti = blockIdx.x >> 4;
    const int tj = blockIdx.x & 15;
    const int i0 = ti * 64, j0 = tj * 64;

    __shared__ float sbuf[2 * 64 * 68];
    __shared__ float sx2[64], sy2[64];
    float* xs = sbuf;
    float* ys = sbuf + 64 * 68;

    const int tid = threadIdx.x;
    const float4* xb4 = (const float4*)(x + ((size_t)b * LSEQ + i0) * NCH);
    const float4* yb4 = (const float4*)(y + ((size_t)b * LSEQ + j0) * NCH);

#pragma unroll
    for (int k = 0; k < 4; k++) {
        int e = tid + 256 * k;
        int r = e >> 4, c4v = e & 15;
        float4 vx = xb4[r * 16 + c4v];
        float4 vy = yb4[r * 16 + c4v];
        vx.x = __uint_as_float(f2tf32(vx.x)); vx.y = __uint_as_float(f2tf32(vx.y));
        vx.z = __uint_as_float(f2tf32(vx.z)); vx.w = __uint_as_float(f2tf32(vx.w));
        vy.x = __uint_as_float(f2tf32(vy.x)); vy.y = __uint_as_float(f2tf32(vy.y));
        vy.z = __uint_as_float(f2tf32(vy.z)); vy.w = __uint_as_float(f2tf32(vy.w));
        *(float4*)&xs[r * 68 + c4v * 4] = vx;
        *(float4*)&ys[r * 68 + c4v * 4] = vy;
    }
    __syncthreads();

    if (tid < 64) {
        float s = 0.f;
#pragma unroll
        for (int c = 0; c < 64; c++) { float v = xs[tid * 68 + c]; s += v * v; }
        sx2[tid] = s;
    } else if (tid < 128) {
        int r = tid - 64;
        float s = 0.f;
#pragma unroll
        for (int c = 0; c < 64; c++) { float v = ys[r * 68 + c]; s += v * v; }
        sy2[r] = s;
    }
    __syncthreads();

    const int wrp  = tid >> 5, lane = tid & 31;
    const int wr   = wrp & 3, wc = wrp >> 2;
    const int r4   = lane >> 2, c4 = lane & 3;
    const float* As = xs + (wr * 16) * 68;
    const float* Bs = ys + (wc * 32) * 68;

    float cc[4][4];
#pragma unroll
    for (int nt = 0; nt < 4; nt++)
#pragma unroll
        for (int q = 0; q < 4; q++) cc[nt][q] = 0.f;

#pragma unroll
    for (int k0 = 0; k0 < 64; k0 += 8) {
        uint32_t a0 = __float_as_uint(As[(r4)     * 68 + k0 + c4]);
        uint32_t a1 = __float_as_uint(As[(r4 + 8) * 68 + k0 + c4]);
        uint32_t a2 = __float_as_uint(As[(r4)     * 68 + k0 + c4 + 4]);
        uint32_t a3 = __float_as_uint(As[(r4 + 8) * 68 + k0 + c4 + 4]);
#pragma unroll
        for (int nt = 0; nt < 4; nt++) {
            uint32_t b0 = __float_as_uint(Bs[(nt * 8 + r4) * 68 + k0 + c4]);
            uint32_t b1 = __float_as_uint(Bs[(nt * 8 + r4) * 68 + k0 + c4 + 4]);
            asm volatile(
                "mma.sync.aligned.m16n8k8.row.col.f32.tf32.tf32.f32 "
                "{%0,%1,%2,%3}, {%4,%5,%6,%7}, {%8,%9}, {%0,%1,%2,%3};"
                : "+f"(cc[nt][0]), "+f"(cc[nt][1]), "+f"(cc[nt][2]), "+f"(cc[nt][3])
                : "r"(a0), "r"(a1), "r"(a2), "r"(a3), "r"(b0), "r"(b1));
        }
    }
    __syncthreads();

    float* Dt = sbuf;                 /* Dt_T[jl][il], stride 67 */
    const int row0 = wr * 16 + r4;
#pragma unroll
    for (int nt = 0; nt < 4; nt++) {
        int colb = wc * 32 + nt * 8 + 2 * c4;
        Dt[colb * 67 + row0]           = (sx2[row0]     + sy2[colb]     - 2.0f * cc[nt][0]) * LOG2E;
        Dt[(colb + 1) * 67 + row0]     = (sx2[row0]     + sy2[colb + 1] - 2.0f * cc[nt][1]) * LOG2E;
        Dt[colb * 67 + row0 + 8]       = (sx2[row0 + 8] + sy2[colb]     - 2.0f * cc[nt][2]) * LOG2E;
        Dt[(colb + 1) * 67 + row0 + 8] = (sx2[row0 + 8] + sy2[colb + 1] - 2.0f * cc[nt][3]) * LOG2E;
    }
    __syncthreads();

    const int h  = wrp & 1;
    const int w4 = wrp >> 1;
    const size_t gbase = ((size_t)(b * 32 + ti * 2 + h) * NSTEP + j0) * 32;
    for (int so = w4; so < 95; so += 4) {
        int jl = so - lane;
        if (jl >= 0 && jl < 64) {
            g_D1[gbase + (size_t)so * 32 + lane] = Dt[jl * 67 + 32 * h + lane];
        }
    }
}

/* ------------------------------------------------------------------ */
/* Kernel B: 2-CTA cluster per batch, 16 warps each (128 SMs total).   */
/* Rank 0 = rows 1..512, rank 1 = rows 513..1024. Global warp          */
/* g = rank*16+w runs chunk c at round c + KOFF*g. Row-511 boundary    */
/* streamed into rank 1's bnd[] via st.shared::cluster by rank 0's     */
/* warp 15 lane 31, one mbarrier arrive per chunk. Consumer warp 0     */
/* waits for producer chunk c+4 (1-round slack by schedule).           */
/* ------------------------------------------------------------------ */
#define CH      8
#define NCHUNK  132
#define KOFF    5
#define NWARP   16

__global__ void __launch_bounds__(512) __cluster_dims__(2, 1, 1)
sdtw_pipeline_kernel(float* __restrict__ out) {
    const int b    = blockIdx.x >> 1;
    const int cons = blockIdx.x & 1;         /* cluster rank */
    const int tid  = threadIdx.x;
    const int w    = tid >> 5;
    const int l    = tid & 31;

    __shared__ float    rb[NWARP - 1][128];  /* intra-CTA boundary rings */
    __shared__ float    bnd[1060];           /* R[512][j] stream (used in rank 1) */
    __shared__ uint64_t mbar[NCHUNK];

    for (int e = tid; e < (NWARP - 1) * 128; e += 512) ((float*)rb)[e] = BIGC;
    for (int e = tid; e < 1060; e += 512) bnd[e] = BIGC;
    if (tid < NCHUNK) {
        uint32_t ma = smem_u32(&mbar[tid]);
        asm volatile("mbarrier.init.shared.b64 [%0], 1;" :: "r"(ma) : "memory");
    }
    __syncthreads();
    asm volatile("barrier.cluster.arrive.aligned;" ::: "memory");
    asm volatile("barrier.cluster.wait.aligned;"   ::: "memory");

    /* producer's remote (rank 1) addresses */
    uint32_t bnd_rem, mbar_rem;
    {
        uint32_t bl = smem_u32(bnd), ml = smem_u32(mbar);
        asm("mapa.shared::cluster.u32 %0, %1, %2;" : "=r"(bnd_rem)  : "r"(bl), "r"(1));
        asm("mapa.shared::cluster.u32 %0, %1, %2;" : "=r"(mbar_rem) : "r"(ml), "r"(1));
    }

    float v1     = BIGC;                                      /* left operand    */
    float u_prev = (cons == 0 && w == 0 && l == 0) ? 0.0f : BIGC; /* diag       */
    float result = 0.0f;

    const int gstrip = cons * NWARP + w;     /* global strip 0..31 */
    const float* dp  = g_D1 + ((size_t)(b * 32 + gstrip) * NSTEP) * 32 + l;
    float*       rbw = (w < NWARP - 1) ? rb[w] : rb[0];
    const float* rbr = (w > 0) ? rb[w - 1] : rb[0];

    const int coff    = KOFF * (cons * NWARP + w);  /* round offset of this warp */
    const int nrounds = cons ? (KOFF * 31 + NCHUNK) : (KOFF * 15 + NCHUNK); /* 287 / 207 */

    float dv[CH];
    if (cons == 0 && w == 0) {
#pragma unroll
        for (int k = 0; k < CH; k++) dv[k] = dp[(size_t)k * 32];
    }

    for (int r = 0; r < nrounds; r++) {
        const int c  = r - coff;
        const int cn = c + 1;

        /* prefetch next chunk */
        float dn[CH];
        const bool pf = (cn >= 0) && (cn < NCHUNK);
        if (pf) {
            const float* dpn = dp + (size_t)(cn * CH) * 32;
#pragma unroll
            for (int k = 0; k < CH; k++) dn[k] = dpn[(size_t)k * 32];
        }

        if (c >= 0 && c < NCHUNK) {
            /* consumer warp 0 waits for producer chunk c+4 */
            if (cons && w == 0) {
                int need = c + 4; if (need > NCHUNK - 1) need = NCHUNK - 1;
                uint32_t ma = smem_u32(&mbar[need]);
                uint32_t done;
                asm volatile(
                    "{.reg .pred p;\n\t"
                    "mbarrier.try_wait.parity.acquire.cta.shared::cta.b64 p, [%1], 0;\n\t"
                    "selp.b32 %0, 1, 0, p;}\n" : "=r"(done) : "r"(ma) : "memory");
                if (!done) {
                    asm volatile(
                        "{.reg .pred P1;\n\t"
                        "W_%=:\n\t"
                        "mbarrier.try_wait.parity.acquire.cta.shared::cta.b64 P1, [%0], 0, 0x989680;\n\t"
                        "@P1 bra D_%=;\n\t"
                        "bra W_%=;\n\t"
                        "D_%=:}\n" :: "r"(ma) : "memory");
                }
                asm volatile("fence.acq_rel.cluster;" ::: "memory");
            }

            const int sc = c * CH;
#pragma unroll
            for (int k = 0; k < CH; k++) {
                const int s = sc + k;
                float rv;
                if (w == 0) rv = cons ? bnd[s + 1] : BIGC;   /* warp-uniform branch */
                else        rv = rbr[(s + 1) & 127];
                float u = __shfl_up_sync(0xffffffffu, v1, 1);
                if (l == 0) u = rv;
                float nv = dv[k] + softmin3(u_prev, u, v1);
                if (l == 31) {
                    if (w < NWARP - 1) {
                        rbw[(s - 30) & 127] = nv;
                    } else if (!cons) {
                        if (s >= 30) {
                            asm volatile("st.shared::cluster.f32 [%0], %1;"
                                         :: "r"(bnd_rem + 4u * (uint32_t)(s - 30)), "f"(nv)
                                         : "memory");
                        }
                    } else if (s == 1054) {
                        result = nv;                         /* R[1024][1024] */
                    }
                }
                v1     = nv;
                u_prev = u;
            }

            /* producer signals chunk completion */
            if (!cons && w == NWARP - 1 && l == 31) {
                asm volatile("fence.acq_rel.cluster;" ::: "memory");
                asm volatile("mbarrier.arrive.shared::cluster.b64 _, [%0];"
                             :: "r"(mbar_rem + 8u * (uint32_t)c) : "memory");
            }
        }

        if (pf) {
#pragma unroll
            for (int k = 0; k < CH; k++) dv[k] = dn[k];
        }
        __syncthreads();
    }

    if (cons && w == NWARP - 1 && l == 31) out[b] = result * LN2F;

    asm volatile("barrier.cluster.arrive.aligned;" ::: "memory");
    asm volatile("barrier.cluster.wait.aligned;"   ::: "memory");
}

/* ------------------------------------------------------------------ */
extern "C" void kernel_launch(void* const* d_in, const int* in_sizes, int n_in,
                              void* d_out, int out_size) {
    (void)in_sizes; (void)n_in; (void)out_size;
    const float* x = (const float*)d_in[0];
    const float* y = (const float*)d_in[1];
    float* out = (float*)d_out;

    dim3 gridA(256, NBATCH);
    compute_D_kernel<<<gridA, 256>>>(x, y);
    sdtw_pipeline_kernel<<<2 * NBATCH, 512>>>(out);
}

// round 10
// speedup vs baseline: 1.5272x; 1.5272x over previous
#include <cuda_runtime.h>
#include <math.h>
#include <cstdint>

#define LSEQ   1024
#define NBATCH 64
#define NCH    64
#define NSTEP  1056          /* steps per strip: 1024 + 31 + pad */
#define BIGC   1.0e10f
#define LOG2E  1.4426950408889634f
#define LN2F   0.6931471805599453f

/* Strip-step-major scratch: g_D1[b][w][s][l] = D[32w+l][s-l] * log2(e).
   277 MB. Slots with s-l outside [0,1023] are never written and stay 0. */
__device__ float g_D1[(size_t)NBATCH * 32 * NSTEP * 32];

__device__ __forceinline__ float ex2(float z) {
    float r; asm("ex2.approx.f32 %0, %1;" : "=f"(r) : "f"(z)); return r;
}
__device__ __forceinline__ float lg2(float z) {
    float r; asm("lg2.approx.f32 %0, %1;" : "=f"(r) : "f"(z)); return r;
}
__device__ __forceinline__ uint32_t f2tf32(float v) {
    uint32_t r; asm("cvt.rna.tf32.f32 %0, %1;" : "=r"(r) : "f"(v)); return r;
}
__device__ __forceinline__ uint32_t smem_u32(const void* p) {
    uint32_t a;
    asm("{ .reg .u64 t; cvta.to.shared.u64 t, %1; cvt.u32.u64 %0, t; }" : "=r"(a) : "l"(p));
    return a;
}
/* softmin in base-2 domain: -log2(2^-a + 2^-u + 2^-lf), 3 MUFU */
__device__ __forceinline__ float softmin3(float a, float u, float lf) {
    float mn1 = fminf(a, u);
    float mx1 = fmaxf(a, u);
    float m   = fminf(mn1, lf);
    float M   = fmaxf(mx1, lf);
    float med = fmaxf(mn1, fminf(mx1, lf));
    float e   = 1.0f + ex2(m - med) + ex2(m - M);
    return m - lg2(e);
}

/* ------------------------------------------------------------------ */
/* Kernel A: D = (x2 + y2 - 2*x.y^T) * log2(e) via tf32 mma.sync,     */
/* written into the strip-step-major layout g_D1. (unchanged from R8)  */
/* ------------------------------------------------------------------ */
__global__ void __launch_bounds__(256)
compute_D_kernel(const float* __restrict__ x, const float* __restrict__ y) {
    const int b  = blockIdx.y;
    const int ti = blockIdx.x >> 4;
    const int tj = blockIdx.x & 15;
    const int i0 = ti * 64, j0 = tj * 64;

    __shared__ float sbuf[2 * 64 * 68];
    __shared__ float sx2[64], sy2[64];
    float* xs = sbuf;
    float* ys = sbuf + 64 * 68;

    const int tid = threadIdx.x;
    const float4* xb4 = (const float4*)(x + ((size_t)b * LSEQ + i0) * NCH);
    const float4* yb4 = (const float4*)(y + ((size_t)b * LSEQ + j0) * NCH);

#pragma unroll
    for (int k = 0; k < 4; k++) {
        int e = tid + 256 * k;
        int r = e >> 4, c4v = e & 15;
        float4 vx = xb4[r * 16 + c4v];
        float4 vy = yb4[r * 16 + c4v];
        vx.x = __uint_as_float(f2tf32(vx.x)); vx.y = __uint_as_float(f2tf32(vx.y));
        vx.z = __uint_as_float(f2tf32(vx.z)); vx.w = __uint_as_float(f2tf32(vx.w));
        vy.x = __uint_as_float(f2tf32(vy.x)); vy.y = __uint_as_float(f2tf32(vy.y));
        vy.z = __uint_as_float(f2tf32(vy.z)); vy.w = __uint_as_float(f2tf32(vy.w));
        *(float4*)&xs[r * 68 + c4v * 4] = vx;
        *(float4*)&ys[r * 68 + c4v * 4] = vy;
    }
    __syncthreads();

    if (tid < 64) {
        float s = 0.f;
#pragma unroll
        for (int c = 0; c < 64; c++) { float v = xs[tid * 68 + c]; s += v * v; }
        sx2[tid] = s;
    } else if (tid < 128) {
        int r = tid - 64;
        float s = 0.f;
#pragma unroll
        for (int c = 0; c < 64; c++) { float v = ys[r * 68 + c]; s += v * v; }
        sy2[r] = s;
    }
    __syncthreads();

    const int wrp  = tid >> 5, lane = tid & 31;
    const int wr   = wrp & 3, wc = wrp >> 2;
    const int r4   = lane >> 2, c4 = lane & 3;
    const float* As = xs + (wr * 16) * 68;
    const float* Bs = ys + (wc * 32) * 68;

    float cc[4][4];
#pragma unroll
    for (int nt = 0; nt < 4; nt++)
#pragma unroll
        for (int q = 0; q < 4; q++) cc[nt][q] = 0.f;

#pragma unroll
    for (int k0 = 0; k0 < 64; k0 += 8) {
        uint32_t a0 = __float_as_uint(As[(r4)     * 68 + k0 + c4]);
        uint32_t a1 = __float_as_uint(As[(r4 + 8) * 68 + k0 + c4]);
        uint32_t a2 = __float_as_uint(As[(r4)     * 68 + k0 + c4 + 4]);
        uint32_t a3 = __float_as_uint(As[(r4 + 8) * 68 + k0 + c4 + 4]);
#pragma unroll
        for (int nt = 0; nt < 4; nt++) {
            uint32_t b0 = __float_as_uint(Bs[(nt * 8 + r4) * 68 + k0 + c4]);
            uint32_t b1 = __float_as_uint(Bs[(nt * 8 + r4) * 68 + k0 + c4 + 4]);
            asm volatile(
                "mma.sync.aligned.m16n8k8.row.col.f32.tf32.tf32.f32 "
                "{%0,%1,%2,%3}, {%4,%5,%6,%7}, {%8,%9}, {%0,%1,%2,%3};"
                : "+f"(cc[nt][0]), "+f"(cc[nt][1]), "+f"(cc[nt][2]), "+f"(cc[nt][3])
                : "r"(a0), "r"(a1), "r"(a2), "r"(a3), "r"(b0), "r"(b1));
        }
    }
    __syncthreads();

    float* Dt = sbuf;                 /* Dt_T[jl][il], stride 67 */
    const int row0 = wr * 16 + r4;
#pragma unroll
    for (int nt = 0; nt < 4; nt++) {
        int colb = wc * 32 + nt * 8 + 2 * c4;
        Dt[colb * 67 + row0]           = (sx2[row0]     + sy2[colb]     - 2.0f * cc[nt][0]) * LOG2E;
        Dt[(colb + 1) * 67 + row0]     = (sx2[row0]     + sy2[colb + 1] - 2.0f * cc[nt][1]) * LOG2E;
        Dt[colb * 67 + row0 + 8]       = (sx2[row0 + 8] + sy2[colb]     - 2.0f * cc[nt][2]) * LOG2E;
        Dt[(colb + 1) * 67 + row0 + 8] = (sx2[row0 + 8] + sy2[colb + 1] - 2.0f * cc[nt][3]) * LOG2E;
    }
    __syncthreads();

    const int h  = wrp & 1;
    const int w4 = wrp >> 1;
    const size_t gbase = ((size_t)(b * 32 + ti * 2 + h) * NSTEP + j0) * 32;
    for (int so = w4; so < 95; so += 4) {
        int jl = so - lane;
        if (jl >= 0 && jl < 64) {
            g_D1[gbase + (size_t)so * 32 + lane] = Dt[jl * 67 + 32 * h + lane];
        }
    }
}

/* ------------------------------------------------------------------ */
/* Kernel B: ASYNC dataflow soft-DTW. 32 warps, 1 row/lane. No block  */
/* barrier: warp w spins on warp w-1's progress flag (acquire) until   */
/* it is 40 steps ahead, then runs its 8-step chunk. Full-length smem  */
/* rings (no wrap, no backpressure). Writer publishes with release.    */
/* ------------------------------------------------------------------ */
#define CH       8
#define NCHUNK   132                    /* 132*8 = 1056 steps per warp */
#define RINGPAD  1092                   /* >= 1055 + 31 + pad */

__global__ void __launch_bounds__(1024)
sdtw_async_kernel(float* __restrict__ out) {
    extern __shared__ float sm[];
    float* rb   = sm;                          /* [31][RINGPAD] */
    int*   prog = (int*)(sm + 31 * RINGPAD);   /* [32] progress flags */

    const int b   = blockIdx.x;
    const int tid = threadIdx.x;
    const int w   = tid >> 5;
    const int l   = tid & 31;

    for (int e = tid; e < 31 * RINGPAD; e += 1024) rb[e] = BIGC;
    if (tid < 32) prog[tid] = 0;
    __syncthreads();                            /* the ONLY block barrier */

    float v1     = BIGC;                             /* left operand   */
    float u_prev = (w == 0 && l == 0) ? 0.0f : BIGC; /* diag operand   */
    float result = 0.0f;

    const float* dp  = g_D1 + ((size_t)(b * 32 + w) * NSTEP) * 32 + l;
    float*       rbw = rb + (size_t)(w < 31 ? w : 0) * RINGPAD;
    const float* rbr = rb + (size_t)(w > 0 ? w - 1 : 0) * RINGPAD;
    const uint32_t prog_w  = smem_u32(&prog[w]);
    const uint32_t prog_pr = smem_u32(&prog[w > 0 ? w - 1 : 0]);

    float dv[CH];
#pragma unroll
    for (int k = 0; k < CH; k++) dv[k] = dp[(size_t)k * 32];

    for (int c = 0; c < NCHUNK; c++) {
        /* prefetch next chunk while (possibly) waiting */
        float dn[CH];
        const bool pf = (c + 1) < NCHUNK;
        if (pf) {
            const float* dpn = dp + (size_t)((c + 1) * CH) * 32;
#pragma unroll
            for (int k = 0; k < CH; k++) dn[k] = dpn[(size_t)k * 32];
        }

        if (w > 0) {
            int need = 8 * c + 39;
            if (need > 8 * NCHUNK) need = 8 * NCHUNK;   /* writer max = 1056 */
            int pv;
            asm volatile("ld.acquire.cta.shared.b32 %0, [%1];"
                         : "=r"(pv) : "r"(prog_pr) : "memory");
            while (pv < need) {
                __nanosleep(64);
                asm volatile("ld.acquire.cta.shared.b32 %0, [%1];"
                             : "=r"(pv) : "r"(prog_pr) : "memory");
            }
        }

        const int sc = c * CH;
#pragma unroll
        for (int k = 0; k < CH; k++) {
            const int s = sc + k;
            float rv = rbr[s + 31];                     /* broadcast LDS */
            float u  = __shfl_up_sync(0xffffffffu, v1, 1);
            if (l == 0) u = (w == 0) ? BIGC : rv;
            float nv = dv[k] + softmin3(u_prev, u, v1);
            if (l == 31) {
                if (w < 31) rbw[s] = nv;
                else if (s == 1054) result = nv;        /* R[1024][1024] */
            }
            v1     = nv;
            u_prev = u;
        }

        if (w < 31 && l == 31) {
            asm volatile("st.release.cta.shared.b32 [%0], %1;"
                         :: "r"(prog_w), "r"(8 * (c + 1)) : "memory");
        }

        if (pf) {
#pragma unroll
            for (int k = 0; k < CH; k++) dv[k] = dn[k];
        }
    }

    if (w == 31 && l == 31) out[b] = result * LN2F;
}

/* ------------------------------------------------------------------ */
extern "C" void kernel_launch(void* const* d_in, const int* in_sizes, int n_in,
                              void* d_out, int out_size) {
    (void)in_sizes; (void)n_in; (void)out_size;
    const float* x = (const float*)d_in[0];
    const float* y = (const float*)d_in[1];
    float* out = (float*)d_out;

    static int smem_set = 0;
    const int smem_b = (31 * RINGPAD + 32) * (int)sizeof(float);
    if (!smem_set) {
        cudaFuncSetAttribute(sdtw_async_kernel,
                             cudaFuncAttributeMaxDynamicSharedMemorySize, smem_b);
        smem_set = 1;
    }

    dim3 gridA(256, NBATCH);
    compute_D_kernel<<<gridA, 256>>>(x, y);
    sdtw_async_kernel<<<NBATCH, 1024, smem_b>>>(out);
}